// round 1
// baseline (speedup 1.0000x reference)
#include <cuda_runtime.h>
#include <cuda_bf16.h>

// Problem: QSRGAN quantum super-resolution.
// x: [256,256,5] f32, q_params: [4,30] f32 -> out: [4,512,512,16] f32.
//
// Strategy:
//  - Kernel 1 (tiny): build per-generator circuit matrix rows 0..15 of the
//    fixed 32x32 unitary (6 layers of RY(weights)+CZ), by evolving the 32
//    basis columns. Stored as W[g][j][i] (column-major over j).
//  - Kernel 2: per pixel: bilinear-upsample 5 angles, build rank-1 product
//    state (32 amps), then per generator a 16x32 matvec from shared memory,
//    square, max-normalize (the sum-normalization cancels algebraically).

#define DIM 32
#define KEEPN 16
#define NGEN 4
#define OW 512
#define IW 256
#define NPIX (OW*OW)

__device__ float g_W[NGEN][DIM][KEEPN];   // [generator][column j][row i]

// ---------------------------------------------------------------------------
// Kernel 1: precompute circuit matrices (4 blocks x 32 threads)
// ---------------------------------------------------------------------------
__global__ void precompute_W_kernel(const float* __restrict__ qp)
{
    const int g = blockIdx.x;      // generator
    const int j = threadIdx.x;     // basis column

    float st[DIM];
#pragma unroll
    for (int i = 0; i < DIM; i++) st[i] = (i == j) ? 1.0f : 0.0f;

#pragma unroll
    for (int d = 0; d < 6; d++) {
#pragma unroll
        for (int q = 0; q < 5; q++) {
            float th = 0.5f * qp[g * 30 + d * 5 + q];
            float s, c;
            sincosf(th, &s, &c);
            const int r = 1 << (4 - q);   // stride for this wire
#pragma unroll
            for (int i = 0; i < DIM; i++) {
                if ((i & r) == 0) {
                    float a0 = st[i];
                    float a1 = st[i | r];
                    st[i]     = c * a0 - s * a1;
                    st[i | r] = s * a0 + c * a1;
                }
            }
        }
        // CZ ladder: sign flip if odd # of adjacent (bit k+1,bit k) pairs set
#pragma unroll
        for (int i = 0; i < DIM; i++) {
            if (__popc(i & (i >> 1)) & 1) st[i] = -st[i];
        }
    }

#pragma unroll
    for (int i = 0; i < KEEPN; i++) g_W[g][j][i] = st[i];
}

// ---------------------------------------------------------------------------
// Kernel 2: main per-pixel kernel (1024 blocks x 256 threads)
// ---------------------------------------------------------------------------
__global__ __launch_bounds__(256) void qsrgan_main_kernel(
    const float* __restrict__ x, float* __restrict__ out)
{
    // Shared copy of W: 4 gens * 32 cols * 16 rows = 2048 floats = 8 KB.
    __shared__ float4 sW[NGEN * DIM * 4];   // [g][j][4xfloat4]

    const int tid = threadIdx.x;
    {
        const float4* gw = reinterpret_cast<const float4*>(g_W);
        sW[tid]       = gw[tid];
        sW[tid + 256] = gw[tid + 256];
    }
    __syncthreads();

    const int p  = blockIdx.x * 256 + tid;
    const int oy = p >> 9;          // 512 wide
    const int ox = p & 511;

    // ---- bilinear upsample (half-pixel centers, scale 2) ----
    float syf = oy * 0.5f - 0.25f;
    int   y0  = __float2int_rd(syf);
    float fy  = syf - (float)y0;
    int y0c = max(y0, 0);
    int y1c = min(y0 + 1, IW - 1);

    float sxf = ox * 0.5f - 0.25f;
    int   x0  = __float2int_rd(sxf);
    float fx  = sxf - (float)x0;
    int x0c = max(x0, 0);
    int x1c = min(x0 + 1, IW - 1);

    const float* p00 = x + (y0c * IW + x0c) * 5;
    const float* p01 = x + (y0c * IW + x1c) * 5;
    const float* p10 = x + (y1c * IW + x0c) * 5;
    const float* p11 = x + (y1c * IW + x1c) * 5;

    float cc[5], ss[5];
#pragma unroll
    for (int c = 0; c < 5; c++) {
        float v00 = __ldg(p00 + c);
        float v01 = __ldg(p01 + c);
        float v10 = __ldg(p10 + c);
        float v11 = __ldg(p11 + c);
        float top = v00 + fx * (v01 - v00);
        float bot = v10 + fx * (v11 - v10);
        float a   = top + fy * (bot - top);

        // half-angle t in [0, 0.5] -> Taylor sin/cos (avoids MUFU pressure)
        float t  = 0.5f * a;
        float t2 = t * t;
        ss[c] = t * (1.0f + t2 * (-1.0f / 6.0f + t2 * (1.0f / 120.0f)));
        cc[c] = 1.0f + t2 * (-0.5f + t2 * (1.0f / 24.0f + t2 * (-1.0f / 720.0f)));
    }

    // ---- rank-1 product state: bit (4-q) of index selects cos/sin of wire q
    float st[DIM];
    {
        float t01[4];
#pragma unroll
        for (int i = 0; i < 4; i++)
            t01[i] = ((i >> 1) ? ss[0] : cc[0]) * ((i & 1) ? ss[1] : cc[1]);
        float t012[8];
#pragma unroll
        for (int i = 0; i < 8; i++)
            t012[i] = t01[i >> 1] * ((i & 1) ? ss[2] : cc[2]);
        float t0123[16];
#pragma unroll
        for (int i = 0; i < 16; i++)
            t0123[i] = t012[i >> 1] * ((i & 1) ? ss[3] : cc[3]);
#pragma unroll
        for (int i = 0; i < DIM; i++)
            st[i] = t0123[i >> 1] * ((i & 1) ? ss[4] : cc[4]);
    }

    // ---- per generator: 16x32 matvec + square + max-normalize ----
#pragma unroll 1
    for (int g = 0; g < NGEN; g++) {
        const float4* wg = &sW[g * DIM * 4];

        float acc[KEEPN];
#pragma unroll
        for (int i = 0; i < KEEPN; i++) acc[i] = 0.0f;

#pragma unroll
        for (int j = 0; j < DIM; j++) {
            float sj = st[j];
            float4 w0 = wg[j * 4 + 0];
            float4 w1 = wg[j * 4 + 1];
            float4 w2 = wg[j * 4 + 2];
            float4 w3 = wg[j * 4 + 3];
            acc[0]  = fmaf(w0.x, sj, acc[0]);
            acc[1]  = fmaf(w0.y, sj, acc[1]);
            acc[2]  = fmaf(w0.z, sj, acc[2]);
            acc[3]  = fmaf(w0.w, sj, acc[3]);
            acc[4]  = fmaf(w1.x, sj, acc[4]);
            acc[5]  = fmaf(w1.y, sj, acc[5]);
            acc[6]  = fmaf(w1.z, sj, acc[6]);
            acc[7]  = fmaf(w1.w, sj, acc[7]);
            acc[8]  = fmaf(w2.x, sj, acc[8]);
            acc[9]  = fmaf(w2.y, sj, acc[9]);
            acc[10] = fmaf(w2.z, sj, acc[10]);
            acc[11] = fmaf(w2.w, sj, acc[11]);
            acc[12] = fmaf(w3.x, sj, acc[12]);
            acc[13] = fmaf(w3.y, sj, acc[13]);
            acc[14] = fmaf(w3.z, sj, acc[14]);
            acc[15] = fmaf(w3.w, sj, acc[15]);
        }

        float pr[KEEPN];
        float m = 0.0f;
#pragma unroll
        for (int i = 0; i < KEEPN; i++) {
            pr[i] = acc[i] * acc[i];
            m = fmaxf(m, pr[i]);
        }
        float inv = __fdividef(1.0f, m);

        float4* o = reinterpret_cast<float4*>(
            out + ((size_t)g * NPIX + (size_t)p) * KEEPN);
#pragma unroll
        for (int v = 0; v < 4; v++) {
            float4 ov;
            ov.x = pr[v * 4 + 0] * inv;
            ov.y = pr[v * 4 + 1] * inv;
            ov.z = pr[v * 4 + 2] * inv;
            ov.w = pr[v * 4 + 3] * inv;
            o[v] = ov;
        }
    }
}

// ---------------------------------------------------------------------------
extern "C" void kernel_launch(void* const* d_in, const int* in_sizes, int n_in,
                              void* d_out, int out_size)
{
    const float* x  = (const float*)d_in[0];   // [256,256,5]
    const float* qp = (const float*)d_in[1];   // [4,30]
    float* out = (float*)d_out;                // [4,512,512,16]

    precompute_W_kernel<<<NGEN, DIM>>>(qp);
    qsrgan_main_kernel<<<NPIX / 256, 256>>>(x, out);
}

// round 3
// speedup vs baseline: 1.5303x; 1.5303x over previous
#include <cuda_runtime.h>
#include <cuda_bf16.h>
#include <cstdint>

// QSRGAN: x [256,256,5] f32, q_params [4,30] f32 -> out [4,512,512,16] f32.
//
// Kernel 1: evolve the 32 basis states through the 6-layer RY+CZ circuit per
//   generator -> W[g] (rows 0..15 of the 32x32 unitary). Emit W directly as
//   tf32 hi/lo mma.sync B-fragments (per-lane layout) into g_Bfrag.
// Kernel 2: per pixel build the rank-1 product state (bilinear + poly sincos),
//   stage states in smem, then per 16-pixel tile do the [16x32]x[32x64] GEMM
//   with mma.sync.m16n8k8.tf32 using a 3-term tf32 split (fp32 accuracy).
//   Epilogue: square, per-(row,gen) max via quad shuffles, normalize, store.
//   (sum-normalization cancels algebraically: p/sum/max(p/sum) = p/max(p))

#define DIM 32
#define KEEPN 16
#define NGEN 4
#define OW 512
#define IW 256
#define NPIX (OW*OW)
#define SSTRIDE 36          // state smem row stride (floats), bank-conflict-free

// B fragments: [0..2047] = hi, [2048..4095] = lo.
// index = (pair*32 + lane)*2 + r, pair = ntile*4 + ktile (ntile 0..7, ktile 0..3)
__device__ float g_Bfrag[4096];

__device__ __forceinline__ uint32_t f2tf32(float x) {
    uint32_t u;
    asm("cvt.rna.tf32.f32 %0, %1;" : "=r"(u) : "f"(x));
    return u;
}

#define MMA_TF32(C0,C1,C2,C3, A0,A1,A2,A3, B0,B1)                              \
    asm volatile("mma.sync.aligned.m16n8k8.row.col.f32.tf32.tf32.f32 "         \
                 "{%0,%1,%2,%3}, {%4,%5,%6,%7}, {%8,%9}, {%0,%1,%2,%3};"       \
                 : "+f"(C0), "+f"(C1), "+f"(C2), "+f"(C3)                      \
                 : "r"(A0), "r"(A1), "r"(A2), "r"(A3), "r"(B0), "r"(B1))

// ---------------------------------------------------------------------------
// Kernel 1: precompute circuit matrix fragments (4 blocks x 32 threads)
// ---------------------------------------------------------------------------
__global__ void precompute_W_kernel(const float* __restrict__ qp)
{
    const int g = blockIdx.x;      // generator
    const int j = threadIdx.x;     // basis column (= GEMM k index)

    float st[DIM];
#pragma unroll
    for (int i = 0; i < DIM; i++) st[i] = (i == j) ? 1.0f : 0.0f;

#pragma unroll
    for (int d = 0; d < 6; d++) {
#pragma unroll
        for (int q = 0; q < 5; q++) {
            float th = 0.5f * qp[g * 30 + d * 5 + q];
            float s, c;
            sincosf(th, &s, &c);
            const int r = 1 << (4 - q);
#pragma unroll
            for (int i = 0; i < DIM; i++) {
                if ((i & r) == 0) {
                    float a0 = st[i];
                    float a1 = st[i | r];
                    st[i]     = c * a0 - s * a1;
                    st[i | r] = s * a0 + c * a1;
                }
            }
        }
#pragma unroll
        for (int i = 0; i < DIM; i++) {
            if (__popc(i & (i >> 1)) & 1) st[i] = -st[i];
        }
    }

    // Emit B fragments. B[k=j][n=g*16+i] = st[i].
    // col-major B: lane -> n = 4*(lane>>2 grouping), k covered by (lane&3)+4r.
#pragma unroll
    for (int i = 0; i < KEEPN; i++) {
        float v   = st[i];
        float hif = __uint_as_float(f2tf32(v));
        float lof = __uint_as_float(f2tf32(v - hif));
        int ntile = 2 * g + (i >> 3);
        int ktile = j >> 3;
        int pair  = ntile * 4 + ktile;
        int lane  = ((i & 7) << 2) | (j & 3);
        int r     = (j >> 2) & 1;
        int idx   = (pair * 32 + lane) * 2 + r;
        g_Bfrag[idx]        = hif;
        g_Bfrag[2048 + idx] = lof;
    }
}

// ---------------------------------------------------------------------------
// Kernel 2: main kernel. 1024 blocks x 256 threads, each warp = 32 pixels.
// ---------------------------------------------------------------------------
__global__ void __launch_bounds__(256) qsrgan_mma_kernel(
    const float* __restrict__ x, float* __restrict__ out)
{
    extern __shared__ float smem[];
    float* shB = smem;                 // 4096 floats (hi then lo)
    float* shS = smem + 4096;          // 8 warps * 32 rows * SSTRIDE floats

    const int tid  = threadIdx.x;
    const int lane = tid & 31;
    const int warp = tid >> 5;

    // cooperative load of B fragments (16 KB)
    {
        const float4* src = reinterpret_cast<const float4*>(g_Bfrag);
        float4* dst = reinterpret_cast<float4*>(shB);
#pragma unroll
        for (int t = 0; t < 4; t++) dst[tid + 256 * t] = src[tid + 256 * t];
    }
    __syncthreads();

    // ---- build this thread's pixel state ----
    const int p  = blockIdx.x * 256 + tid;     // my pixel
    const int oy = p >> 9;
    const int ox = p & 511;

    float syf = oy * 0.5f - 0.25f;
    int   y0  = __float2int_rd(syf);
    float fy  = syf - (float)y0;
    int y0c = max(y0, 0);
    int y1c = min(y0 + 1, IW - 1);

    float sxf = ox * 0.5f - 0.25f;
    int   x0  = __float2int_rd(sxf);
    float fx  = sxf - (float)x0;
    int x0c = max(x0, 0);
    int x1c = min(x0 + 1, IW - 1);

    const float* p00 = x + (y0c * IW + x0c) * 5;
    const float* p01 = x + (y0c * IW + x1c) * 5;
    const float* p10 = x + (y1c * IW + x0c) * 5;
    const float* p11 = x + (y1c * IW + x1c) * 5;

    float cc[5], ss[5];
#pragma unroll
    for (int c = 0; c < 5; c++) {
        float v00 = __ldg(p00 + c);
        float v01 = __ldg(p01 + c);
        float v10 = __ldg(p10 + c);
        float v11 = __ldg(p11 + c);
        float top = v00 + fx * (v01 - v00);
        float bot = v10 + fx * (v11 - v10);
        float a   = top + fy * (bot - top);
        float t   = 0.5f * a;                      // t in [0, 0.5]
        float t2  = t * t;
        ss[c] = t * (1.0f + t2 * (-1.0f / 6.0f + t2 * (1.0f / 120.0f)));
        cc[c] = 1.0f + t2 * (-0.5f + t2 * (1.0f / 24.0f + t2 * (-1.0f / 720.0f)));
    }

    float st[DIM];
    {
        float t01[4];
#pragma unroll
        for (int i = 0; i < 4; i++)
            t01[i] = ((i >> 1) ? ss[0] : cc[0]) * ((i & 1) ? ss[1] : cc[1]);
        float t012[8];
#pragma unroll
        for (int i = 0; i < 8; i++)
            t012[i] = t01[i >> 1] * ((i & 1) ? ss[2] : cc[2]);
        float t0123[16];
#pragma unroll
        for (int i = 0; i < 16; i++)
            t0123[i] = t012[i >> 1] * ((i & 1) ? ss[3] : cc[3]);
#pragma unroll
        for (int i = 0; i < DIM; i++)
            st[i] = t0123[i >> 1] * ((i & 1) ? ss[4] : cc[4]);
    }

    // stage state: row = lane within warp, stride SSTRIDE (conflict-free)
    float* Sw = shS + warp * (32 * SSTRIDE);
    {
        float4* row = reinterpret_cast<float4*>(Sw + lane * SSTRIDE);
#pragma unroll
        for (int t = 0; t < 8; t++) {
            float4 v;
            v.x = st[4 * t + 0]; v.y = st[4 * t + 1];
            v.z = st[4 * t + 2]; v.w = st[4 * t + 3];
            row[t] = v;
        }
    }
    __syncwarp();

    const int warpBase = blockIdx.x * 256 + warp * 32;
    const float2* Bhi = reinterpret_cast<const float2*>(shB);
    const float2* Blo = reinterpret_cast<const float2*>(shB + 2048);

    // ---- two 16-pixel m-tiles ----
#pragma unroll
    for (int m = 0; m < 2; m++) {
        // A fragments (hi/lo tf32 split): 4 k-tiles x 4 regs
        uint32_t ahi[4][4], alo[4][4];
        {
            const int r0 = m * 16 + (lane >> 2);
            const int c0 = lane & 3;
#pragma unroll
            for (int kt = 0; kt < 4; kt++) {
                float a0 = Sw[r0 * SSTRIDE       + kt * 8 + c0];
                float a1 = Sw[(r0 + 8) * SSTRIDE + kt * 8 + c0];
                float a2 = Sw[r0 * SSTRIDE       + kt * 8 + c0 + 4];
                float a3 = Sw[(r0 + 8) * SSTRIDE + kt * 8 + c0 + 4];
                ahi[kt][0] = f2tf32(a0);
                ahi[kt][1] = f2tf32(a1);
                ahi[kt][2] = f2tf32(a2);
                ahi[kt][3] = f2tf32(a3);
                alo[kt][0] = f2tf32(a0 - __uint_as_float(ahi[kt][0]));
                alo[kt][1] = f2tf32(a1 - __uint_as_float(ahi[kt][1]));
                alo[kt][2] = f2tf32(a2 - __uint_as_float(ahi[kt][2]));
                alo[kt][3] = f2tf32(a3 - __uint_as_float(ahi[kt][3]));
            }
        }

        float c[8][4];
#pragma unroll
        for (int n = 0; n < 8; n++)
#pragma unroll
            for (int q = 0; q < 4; q++) c[n][q] = 0.0f;

#pragma unroll
        for (int n = 0; n < 8; n++) {
#pragma unroll
            for (int kt = 0; kt < 4; kt++) {
                const int pair = n * 4 + kt;
                float2 bh = Bhi[pair * 32 + lane];
                float2 bl = Blo[pair * 32 + lane];
                uint32_t bh0 = __float_as_uint(bh.x), bh1 = __float_as_uint(bh.y);
                uint32_t bl0 = __float_as_uint(bl.x), bl1 = __float_as_uint(bl.y);
                MMA_TF32(c[n][0], c[n][1], c[n][2], c[n][3],
                         ahi[kt][0], ahi[kt][1], ahi[kt][2], ahi[kt][3], bh0, bh1);
                MMA_TF32(c[n][0], c[n][1], c[n][2], c[n][3],
                         alo[kt][0], alo[kt][1], alo[kt][2], alo[kt][3], bh0, bh1);
                MMA_TF32(c[n][0], c[n][1], c[n][2], c[n][3],
                         ahi[kt][0], ahi[kt][1], ahi[kt][2], ahi[kt][3], bl0, bl1);
            }
        }

        // ---- epilogue: square, per-(row,gen) max over 16 cols, normalize ----
        const int rowA = warpBase + m * 16 + (lane >> 2);     // pixel for c0,c1
        const int rowB = rowA + 8;                            // pixel for c2,c3
        const int colq = 2 * (lane & 3);

#pragma unroll
        for (int g = 0; g < NGEN; g++) {
            // row A values at cols {colq, colq+1, colq+8, colq+9} of this gen
            float xa0 = c[2*g][0]   * c[2*g][0];
            float xa1 = c[2*g][1]   * c[2*g][1];
            float xa2 = c[2*g+1][0] * c[2*g+1][0];
            float xa3 = c[2*g+1][1] * c[2*g+1][1];
            float xb0 = c[2*g][2]   * c[2*g][2];
            float xb1 = c[2*g][3]   * c[2*g][3];
            float xb2 = c[2*g+1][2] * c[2*g+1][2];
            float xb3 = c[2*g+1][3] * c[2*g+1][3];

            float ma = fmaxf(fmaxf(xa0, xa1), fmaxf(xa2, xa3));
            float mb = fmaxf(fmaxf(xb0, xb1), fmaxf(xb2, xb3));
            ma = fmaxf(ma, __shfl_xor_sync(0xffffffffu, ma, 1));
            mb = fmaxf(mb, __shfl_xor_sync(0xffffffffu, mb, 1));
            ma = fmaxf(ma, __shfl_xor_sync(0xffffffffu, ma, 2));
            mb = fmaxf(mb, __shfl_xor_sync(0xffffffffu, mb, 2));
            float ia = __fdividef(1.0f, ma);
            float ib = __fdividef(1.0f, mb);

            float* oa = out + ((size_t)g * NPIX + rowA) * KEEPN;
            float* ob = out + ((size_t)g * NPIX + rowB) * KEEPN;
            *reinterpret_cast<float2*>(oa + colq)     = make_float2(xa0 * ia, xa1 * ia);
            *reinterpret_cast<float2*>(oa + colq + 8) = make_float2(xa2 * ia, xa3 * ia);
            *reinterpret_cast<float2*>(ob + colq)     = make_float2(xb0 * ib, xb1 * ib);
            *reinterpret_cast<float2*>(ob + colq + 8) = make_float2(xb2 * ib, xb3 * ib);
        }
    }
}

// ---------------------------------------------------------------------------
extern "C" void kernel_launch(void* const* d_in, const int* in_sizes, int n_in,
                              void* d_out, int out_size)
{
    const float* x  = (const float*)d_in[0];   // [256,256,5]
    const float* qp = (const float*)d_in[1];   // [4,30]
    float* out = (float*)d_out;                // [4,512,512,16]

    const int smem_bytes = (4096 + 8 * 32 * SSTRIDE) * sizeof(float); // 53248
    cudaFuncSetAttribute(qsrgan_mma_kernel,
                         cudaFuncAttributeMaxDynamicSharedMemorySize, smem_bytes);

    precompute_W_kernel<<<NGEN, DIM>>>(qp);
    qsrgan_mma_kernel<<<NPIX / 256, 256, smem_bytes>>>(x, out);
}